// round 3
// baseline (speedup 1.0000x reference)
#include <cuda_runtime.h>
#include <cuda_fp16.h>
#include <cuda_bf16.h>

#define N_NODES 100000
#define N_EDGES 3200000
#define F_IN 35
#define F_HID 64
#define F_OUT 2

// Scratch (static __device__ arrays; allocation inside kernel_launch is forbidden)
__device__ __align__(16) __half g_h1[N_NODES * F_HID];    // x @ W1 (fp16, halves gather traffic)
__device__ __align__(16) float g_agg1[N_NODES * F_HID];   // aggregated layer-1 (fp32 accum)
__device__ __align__(16) float g_deg[N_NODES];
__device__ __align__(16) float g_dinv[N_NODES];
__device__ __align__(16) float g_h2[N_NODES * F_OUT];     // relu(agg1+b1) @ W2
__device__ __align__(16) float g_agg2[N_NODES * F_OUT];

// ---------------- degree ----------------
__global__ void k_deg_init(int n) {
    int i = blockIdx.x * blockDim.x + threadIdx.x;
    if (i < n) g_deg[i] = 1.0f;  // self-loop weight 1
}

__global__ void k_deg_scatter(const int* __restrict__ ei,
                              const float* __restrict__ ew, int ne) {
    int e = blockIdx.x * blockDim.x + threadIdx.x;
    if (e >= ne) return;
    int dst = ei[ne + e];
    atomicAdd(&g_deg[dst], ew[e]);
}

__global__ void k_dinv(int n) {
    int i = blockIdx.x * blockDim.x + threadIdx.x;
    if (i < n) {
        float d = g_deg[i];
        g_dinv[i] = (d > 0.0f) ? rsqrtf(d) : 0.0f;
    }
}

// ---------------- layer-1 GEMM: h1 = x@W1 (fp16 out), agg1 init = dinv^2 * h1 ----
// W1 columns live in registers: lane owns output cols (2*lane, 2*lane+1).
// One LDS broadcast per k instead of three.
__global__ void __launch_bounds__(256) k_gemm1(const float* __restrict__ x,
                                               const float* __restrict__ W1,
                                               int n, int nwarps_total) {
    __shared__ float sx[8][F_IN + 1];
    int t = threadIdx.x;
    int w = t >> 5, lane = t & 31;
    int gw = blockIdx.x * 8 + w;  // global warp id

    // W1 columns in registers (uniform across warps -> L1 hits after first warp)
    float w0[F_IN], w1[F_IN];
#pragma unroll
    for (int k = 0; k < F_IN; k++) {
        w0[k] = W1[k * F_HID + 2 * lane];
        w1[k] = W1[k * F_HID + 2 * lane + 1];
    }

    for (int row = gw; row < n; row += nwarps_total) {
        // stage the row (35 floats) in shared
        float a = x[(size_t)row * F_IN + lane];
        sx[w][lane] = a;
        if (lane < F_IN - 32) sx[w][32 + lane] = x[(size_t)row * F_IN + 32 + lane];
        __syncwarp();

        float acc0 = 0.f, acc1 = 0.f;
#pragma unroll
        for (int k = 0; k < F_IN; k++) {
            float xv = sx[w][k];
            acc0 += xv * w0[k];
            acc1 += xv * w1[k];
        }
        __syncwarp();

        float dv = g_dinv[row];
        float sl = dv * dv;  // self-loop norm
        reinterpret_cast<__half2*>(g_h1 + (size_t)row * F_HID)[lane] =
            __floats2half2_rn(acc0, acc1);
        reinterpret_cast<float2*>(g_agg1 + (size_t)row * F_HID)[lane] =
            make_float2(sl * acc0, sl * acc1);
    }
}

// ---------------- layer-1 edge scatter: 8 lanes/edge, fp16 gather, red.v4 ------
__global__ void k_scatter1(const int* __restrict__ ei,
                           const float* __restrict__ ew, int ne) {
    int tid = blockIdx.x * blockDim.x + threadIdx.x;
    int e = tid >> 3;
    int lane = tid & 7;
    if (e >= ne) return;
    int src = ei[e];
    int dst = ei[ne + e];
    float norm = g_dinv[src] * ew[e] * g_dinv[dst];
    // 8 halves = 16 bytes per lane
    const float4 raw = reinterpret_cast<const float4*>(g_h1 + (size_t)src * F_HID)[lane];
    const __half2* hp = reinterpret_cast<const __half2*>(&raw);
    float2 f0 = __half22float2(hp[0]);
    float2 f1 = __half22float2(hp[1]);
    float2 f2 = __half22float2(hp[2]);
    float2 f3 = __half22float2(hp[3]);
    float* p = g_agg1 + (size_t)dst * F_HID + lane * 8;
    asm volatile("red.global.add.v4.f32 [%0], {%1, %2, %3, %4};"
                 :: "l"(p), "f"(f0.x * norm), "f"(f0.y * norm),
                    "f"(f1.x * norm), "f"(f1.y * norm) : "memory");
    asm volatile("red.global.add.v4.f32 [%0], {%1, %2, %3, %4};"
                 :: "l"(p + 4), "f"(f2.x * norm), "f"(f2.y * norm),
                    "f"(f3.x * norm), "f"(f3.y * norm) : "memory");
}

// ---------------- layer-2: relu(agg1+b1) @ W2, agg2 init ----------------
// lane owns cols (2*lane, 2*lane+1) to match gemm1 layout.
__global__ void k_layer2(const float* __restrict__ W2, const float* __restrict__ b1, int n) {
    int w = (blockIdx.x * blockDim.x + threadIdx.x) >> 5;
    int lane = threadIdx.x & 31;
    if (w >= n) return;
    float2 av = reinterpret_cast<const float2*>(g_agg1 + (size_t)w * F_HID)[lane];
    float h0 = fmaxf(av.x + b1[2 * lane],     0.f);
    float h1 = fmaxf(av.y + b1[2 * lane + 1], 0.f);
    float p0 = h0 * W2[(2 * lane) * 2 + 0] + h1 * W2[(2 * lane + 1) * 2 + 0];
    float p1 = h0 * W2[(2 * lane) * 2 + 1] + h1 * W2[(2 * lane + 1) * 2 + 1];
#pragma unroll
    for (int o = 16; o > 0; o >>= 1) {
        p0 += __shfl_xor_sync(0xFFFFFFFFu, p0, o);
        p1 += __shfl_xor_sync(0xFFFFFFFFu, p1, o);
    }
    if (lane == 0) {
        float dv = g_dinv[w];
        float sl = dv * dv;
        g_h2[w * 2 + 0] = p0;
        g_h2[w * 2 + 1] = p1;
        g_agg2[w * 2 + 0] = sl * p0;
        g_agg2[w * 2 + 1] = sl * p1;
    }
}

// ---------------- layer-2 edge scatter: 1 thread per edge, red.v2 ----------------
__global__ void k_scatter2(const int* __restrict__ ei,
                           const float* __restrict__ ew, int ne) {
    int e = blockIdx.x * blockDim.x + threadIdx.x;
    if (e >= ne) return;
    int src = ei[e];
    int dst = ei[ne + e];
    float norm = g_dinv[src] * ew[e] * g_dinv[dst];
    float2 v = *reinterpret_cast<const float2*>(g_h2 + src * 2);
    float* p = g_agg2 + dst * 2;
    asm volatile("red.global.add.v2.f32 [%0], {%1, %2};"
                 :: "l"(p), "f"(v.x * norm), "f"(v.y * norm) : "memory");
}

// ---------------- output: bias + log_softmax ----------------
__global__ void k_out(const float* __restrict__ b2, float* __restrict__ out, int n) {
    int i = blockIdx.x * blockDim.x + threadIdx.x;
    if (i >= n) return;
    float a = g_agg2[i * 2 + 0] + b2[0];
    float b = g_agg2[i * 2 + 1] + b2[1];
    float m = fmaxf(a, b);
    float lse = m + logf(expf(a - m) + expf(b - m));
    out[i * 2 + 0] = a - lse;
    out[i * 2 + 1] = b - lse;
}

extern "C" void kernel_launch(void* const* d_in, const int* in_sizes, int n_in,
                              void* d_out, int out_size) {
    const float* x  = (const float*)d_in[0];
    const int*   ei = (const int*)d_in[1];   // int32 (JAX x64 disabled downcasts int64)
    const float* ew = (const float*)d_in[2];
    const float* W1 = (const float*)d_in[3];
    const float* b1 = (const float*)d_in[4];
    const float* W2 = (const float*)d_in[5];
    const float* b2 = (const float*)d_in[6];
    float* out = (float*)d_out;

    const int n  = in_sizes[0] / F_IN;   // 100000
    const int ne = in_sizes[2];          // 3200000

    k_deg_init<<<(n + 255) / 256, 256>>>(n);
    k_deg_scatter<<<(ne + 255) / 256, 256>>>(ei, ew, ne);
    k_dinv<<<(n + 255) / 256, 256>>>(n);
    {
        const int blocks = 1184;  // 8 blocks/SM * 148 SMs; grid-stride over rows
        k_gemm1<<<blocks, 256>>>(x, W1, n, blocks * 8);
    }
    {
        long long threads = (long long)ne * 8;
        k_scatter1<<<(unsigned)((threads + 255) / 256), 256>>>(ei, ew, ne);
    }
    k_layer2<<<(n * 32 + 255) / 256, 256>>>(W2, b1, n);
    k_scatter2<<<(ne + 255) / 256, 256>>>(ei, ew, ne);
    k_out<<<(n + 255) / 256, 256>>>(b2, out, n);
}

// round 4
// speedup vs baseline: 1.4264x; 1.4264x over previous
#include <cuda_runtime.h>
#include <cuda_fp16.h>
#include <cuda_bf16.h>

#define N_NODES 100000
#define N_EDGES 3200000
#define F_IN 35
#define KPAD 36
#define F_HID 64
#define F_OUT 2
#define SCAN_CHUNK 512
#define SCAN_NBLK ((N_NODES + SCAN_CHUNK - 1) / SCAN_CHUNK)   // 196

// ---- scratch (static; no allocation allowed) ----
__device__ __align__(16) __half g_h1[N_NODES * F_HID];  // x@W1 in fp16
__device__ __align__(16) float  g_h2[N_NODES * F_OUT];  // layer-2 pre-agg features
__device__ float g_deg[N_NODES];
__device__ float g_dinv[N_NODES];
__device__ int   g_count[N_NODES];      // in-degree (no self-loop)
__device__ int   g_count2[N_NODES];     // fill cursors
__device__ int   g_rowptr[N_NODES + 1];
__device__ int   g_bsum[SCAN_NBLK];
__device__ int   g_boff[256];
__device__ __align__(8) int   g_csr_src[N_EDGES];
__device__ __align__(8) float g_csr_nrm[N_EDGES];

// ---------------- init: deg=1 (self loop), count=0 ----------------
__global__ void k_init(int n) {
    int i = blockIdx.x * blockDim.x + threadIdx.x;
    if (i < n) { g_deg[i] = 1.0f; g_count[i] = 0; }
}

// ---------------- degree + count scatter ----------------
__global__ void k_deg_scatter(const int* __restrict__ ei,
                              const float* __restrict__ ew, int ne) {
    int e = blockIdx.x * blockDim.x + threadIdx.x;
    if (e >= ne) return;
    int dst = ei[ne + e];
    atomicAdd(&g_deg[dst], ew[e]);
    atomicAdd(&g_count[dst], 1);
}

__global__ void k_dinv(int n) {
    int i = blockIdx.x * blockDim.x + threadIdx.x;
    if (i < n) {
        float d = g_deg[i];
        g_dinv[i] = (d > 0.0f) ? rsqrtf(d) : 0.0f;
    }
}

// ---------------- 3-phase exclusive scan of g_count -> g_rowptr ----------------
__global__ void k_scan1(int n) {            // grid SCAN_NBLK, 512 thr: block sums
    __shared__ int sh[SCAN_CHUNK];
    int i = blockIdx.x * SCAN_CHUNK + threadIdx.x;
    sh[threadIdx.x] = (i < n) ? g_count[i] : 0;
    __syncthreads();
    for (int o = SCAN_CHUNK / 2; o > 0; o >>= 1) {
        if (threadIdx.x < o) sh[threadIdx.x] += sh[threadIdx.x + o];
        __syncthreads();
    }
    if (threadIdx.x == 0) g_bsum[blockIdx.x] = sh[0];
}

__global__ void k_scan2(int nblk, int n) {  // 1 block, 256 thr: scan of block sums
    __shared__ int sh[256];
    int t = threadIdx.x;
    int v = (t < nblk) ? g_bsum[t] : 0;
    sh[t] = v;
    __syncthreads();
    for (int o = 1; o < 256; o <<= 1) {
        int add = (t >= o) ? sh[t - o] : 0;
        __syncthreads();
        sh[t] += add;
        __syncthreads();
    }
    g_boff[t] = sh[t] - v;                  // exclusive
    if (t == nblk - 1) g_rowptr[n] = sh[t]; // total
}

__global__ void k_scan3(int n) {            // grid SCAN_NBLK, 512 thr: final rowptr
    __shared__ int sh[SCAN_CHUNK];
    int i = blockIdx.x * SCAN_CHUNK + threadIdx.x;
    int v = (i < n) ? g_count[i] : 0;
    sh[threadIdx.x] = v;
    __syncthreads();
    for (int o = 1; o < SCAN_CHUNK; o <<= 1) {
        int add = (threadIdx.x >= o) ? sh[threadIdx.x - o] : 0;
        __syncthreads();
        sh[threadIdx.x] += add;
        __syncthreads();
    }
    if (i < n) {
        g_rowptr[i] = g_boff[blockIdx.x] + sh[threadIdx.x] - v;  // exclusive
        g_count2[i] = 0;
    }
}

// ---------------- CSR fill: (src, norm) per slot ----------------
__global__ void k_csr_fill(const int* __restrict__ ei,
                           const float* __restrict__ ew, int ne) {
    int e = blockIdx.x * blockDim.x + threadIdx.x;
    if (e >= ne) return;
    int src = ei[e];
    int dst = ei[ne + e];
    float nrm = g_dinv[src] * ew[e] * g_dinv[dst];
    int pos = g_rowptr[dst] + atomicAdd(&g_count2[dst], 1);
    g_csr_src[pos] = src;
    g_csr_nrm[pos] = nrm;
}

// ---------------- layer-1 GEMM: h1 = x@W1 (fp16). 2 rows/warp ----------------
__global__ void __launch_bounds__(256) k_gemm1(const float* __restrict__ x,
                                               const float* __restrict__ W1, int n) {
    __shared__ float2 sW2[KPAD][32];      // [k][lane] -> cols (2l, 2l+1); zero-padded k=35
    __shared__ float  sx[8][2][KPAD];     // 8 warps x 2 rows x 36 (float4-aligned rows)
    int t = threadIdx.x, w = t >> 5, lane = t & 31;

    for (int i = t; i < KPAD * 32; i += 256) {
        int k = i >> 5, l = i & 31;
        float2 v = make_float2(0.f, 0.f);
        if (k < F_IN) { v.x = W1[k * F_HID + 2 * l]; v.y = W1[k * F_HID + 2 * l + 1]; }
        sW2[k][l] = v;
    }
    int row0 = blockIdx.x * 16 + w * 2;
#pragma unroll
    for (int r = 0; r < 2; r++) {
        int row = row0 + r;
        if (row < n) {
            sx[w][r][lane] = x[(size_t)row * F_IN + lane];
            if (lane < 4) sx[w][r][32 + lane] =
                (lane < F_IN - 32) ? x[(size_t)row * F_IN + 32 + lane] : 0.f;
        }
    }
    __syncthreads();
    if (row0 >= n) return;

    float acc00 = 0.f, acc01 = 0.f, acc10 = 0.f, acc11 = 0.f;
    const float4* sx40 = reinterpret_cast<const float4*>(sx[w][0]);
    const float4* sx41 = reinterpret_cast<const float4*>(sx[w][1]);
#pragma unroll
    for (int k4 = 0; k4 < KPAD / 4; k4++) {
        float4 x0 = sx40[k4], x1 = sx41[k4];
#pragma unroll
        for (int i = 0; i < 4; i++) {
            float2 wv = sW2[k4 * 4 + i][lane];
            float xv0 = (&x0.x)[i], xv1 = (&x1.x)[i];
            acc00 += xv0 * wv.x; acc01 += xv0 * wv.y;
            acc10 += xv1 * wv.x; acc11 += xv1 * wv.y;
        }
    }
    reinterpret_cast<__half2*>(g_h1 + (size_t)row0 * F_HID)[lane] =
        __floats2half2_rn(acc00, acc01);
    if (row0 + 1 < n)
        reinterpret_cast<__half2*>(g_h1 + (size_t)(row0 + 1) * F_HID)[lane] =
            __floats2half2_rn(acc10, acc11);
}

// ---------------- agg1 (CSR gather) + relu + b1 + GEMV W2 -> h2 ----------------
// warp per dst node; lane owns feature cols (2l, 2l+1)
__global__ void __launch_bounds__(256) k_agg1(const float* __restrict__ W2,
                                              const float* __restrict__ b1, int n) {
    int w = (blockIdx.x * blockDim.x + threadIdx.x) >> 5;
    int lane = threadIdx.x & 31;
    if (w >= n) return;
    int beg = g_rowptr[w], end = g_rowptr[w + 1];
    float dv = g_dinv[w];
    float sl = dv * dv;

    float2 self = __half22float2(
        reinterpret_cast<const __half2*>(g_h1 + (size_t)w * F_HID)[lane]);
    float ax = sl * self.x, ay = sl * self.y;

    for (int j0 = beg; j0 < end; j0 += 32) {
        int j = j0 + lane;
        int s = 0; float nm = 0.f;
        if (j < end) { s = g_csr_src[j]; nm = g_csr_nrm[j]; }
        int cnt = end - j0; if (cnt > 32) cnt = 32;
        for (int i = 0; i < cnt; i += 4) {   // lanes >= cnt hold nm=0 -> contribute 0
            int   s0 = __shfl_sync(0xFFFFFFFFu, s,  i);
            int   s1 = __shfl_sync(0xFFFFFFFFu, s,  i + 1);
            int   s2 = __shfl_sync(0xFFFFFFFFu, s,  i + 2);
            int   s3 = __shfl_sync(0xFFFFFFFFu, s,  i + 3);
            float n0 = __shfl_sync(0xFFFFFFFFu, nm, i);
            float n1 = __shfl_sync(0xFFFFFFFFu, nm, i + 1);
            float n2 = __shfl_sync(0xFFFFFFFFu, nm, i + 2);
            float n3 = __shfl_sync(0xFFFFFFFFu, nm, i + 3);
            float2 f0 = __half22float2(reinterpret_cast<const __half2*>(g_h1 + (size_t)s0 * F_HID)[lane]);
            float2 f1 = __half22float2(reinterpret_cast<const __half2*>(g_h1 + (size_t)s1 * F_HID)[lane]);
            float2 f2 = __half22float2(reinterpret_cast<const __half2*>(g_h1 + (size_t)s2 * F_HID)[lane]);
            float2 f3 = __half22float2(reinterpret_cast<const __half2*>(g_h1 + (size_t)s3 * F_HID)[lane]);
            ax += n0 * f0.x; ay += n0 * f0.y;
            ax += n1 * f1.x; ay += n1 * f1.y;
            ax += n2 * f2.x; ay += n2 * f2.y;
            ax += n3 * f3.x; ay += n3 * f3.y;
        }
    }

    // fused layer-2 input transform
    float h0 = fmaxf(ax + b1[2 * lane],     0.f);
    float h1 = fmaxf(ay + b1[2 * lane + 1], 0.f);
    float p0 = h0 * W2[(2 * lane) * 2 + 0] + h1 * W2[(2 * lane + 1) * 2 + 0];
    float p1 = h0 * W2[(2 * lane) * 2 + 1] + h1 * W2[(2 * lane + 1) * 2 + 1];
#pragma unroll
    for (int o = 16; o > 0; o >>= 1) {
        p0 += __shfl_xor_sync(0xFFFFFFFFu, p0, o);
        p1 += __shfl_xor_sync(0xFFFFFFFFu, p1, o);
    }
    if (lane == 0) {
        g_h2[w * 2 + 0] = p0;
        g_h2[w * 2 + 1] = p1;
    }
}

// ---------------- agg2 (CSR gather) + self + b2 + log_softmax -> out ----------------
__global__ void __launch_bounds__(256) k_agg2(const float* __restrict__ b2,
                                              float* __restrict__ out, int n) {
    int w = (blockIdx.x * blockDim.x + threadIdx.x) >> 5;
    int lane = threadIdx.x & 31;
    if (w >= n) return;
    int beg = g_rowptr[w], end = g_rowptr[w + 1];
    float a0 = 0.f, a1 = 0.f;
    for (int j = beg + lane; j < end; j += 32) {
        int s = g_csr_src[j];
        float nm = g_csr_nrm[j];
        float2 v = *reinterpret_cast<const float2*>(g_h2 + (size_t)s * 2);
        a0 += nm * v.x;
        a1 += nm * v.y;
    }
#pragma unroll
    for (int o = 16; o > 0; o >>= 1) {
        a0 += __shfl_xor_sync(0xFFFFFFFFu, a0, o);
        a1 += __shfl_xor_sync(0xFFFFFFFFu, a1, o);
    }
    if (lane == 0) {
        float dv = g_dinv[w];
        float sl = dv * dv;
        float2 hv = *reinterpret_cast<const float2*>(g_h2 + (size_t)w * 2);
        float A = a0 + sl * hv.x + b2[0];
        float B = a1 + sl * hv.y + b2[1];
        float m = fmaxf(A, B);
        float lse = m + logf(expf(A - m) + expf(B - m));
        out[w * 2 + 0] = A - lse;
        out[w * 2 + 1] = B - lse;
    }
}

extern "C" void kernel_launch(void* const* d_in, const int* in_sizes, int n_in,
                              void* d_out, int out_size) {
    const float* x  = (const float*)d_in[0];
    const int*   ei = (const int*)d_in[1];   // int32 (JAX x64 disabled)
    const float* ew = (const float*)d_in[2];
    const float* W1 = (const float*)d_in[3];
    const float* b1 = (const float*)d_in[4];
    const float* W2 = (const float*)d_in[5];
    const float* b2 = (const float*)d_in[6];
    float* out = (float*)d_out;

    const int n  = in_sizes[0] / F_IN;   // 100000
    const int ne = in_sizes[2];          // 3200000
    const int nblk = (n + SCAN_CHUNK - 1) / SCAN_CHUNK;

    k_init<<<(n + 255) / 256, 256>>>(n);
    k_deg_scatter<<<(ne + 255) / 256, 256>>>(ei, ew, ne);
    k_dinv<<<(n + 255) / 256, 256>>>(n);
    k_scan1<<<nblk, SCAN_CHUNK>>>(n);
    k_scan2<<<1, 256>>>(nblk, n);
    k_scan3<<<nblk, SCAN_CHUNK>>>(n);
    k_csr_fill<<<(ne + 255) / 256, 256>>>(ei, ew, ne);
    k_gemm1<<<(n + 15) / 16, 256>>>(x, W1, n);
    k_agg1<<<(n * 32 + 255) / 256, 256>>>(W2, b1, n);
    k_agg2<<<(n * 32 + 255) / 256, 256>>>(b2, out, n);
}